// round 1
// baseline (speedup 1.0000x reference)
#include <cuda_runtime.h>

#define TOK_TOTAL 32768
#define TILE 128
#define NCTA (TOK_TOTAL / TILE)   // 256

// Scratch for intermediate per-token vectors (8 MB each)
__device__ float g_w12[TOK_TOTAL * 64];
__device__ float g_w21[TOK_TOTAL * 64];

// ---------------------------------------------------------------------------
// Kernel A: w11 = relu(cat @ W11 + b11); w12 = w11 @ W12 + b12;
//           w21 = relu(cat @ W21 + b21)
// smem (floats): catS[128][129]@0  W11s[128*64]@16512  W21s@24704
//                W12s[64*64]@32896  w11S[128][65]@36992  b11/b21/b12@45312
// total 45504 floats = 182016 B
// ---------------------------------------------------------------------------
__global__ __launch_bounds__(256) void prep_kernel(
    const float* __restrict__ img, const float* __restrict__ loc,
    const float* __restrict__ W11, const float* __restrict__ b11,
    const float* __restrict__ W12, const float* __restrict__ b12,
    const float* __restrict__ W21, const float* __restrict__ b21)
{
    extern __shared__ float sm[];
    float* catS = sm;            // [t][129]
    float* W11s = sm + 16512;    // [k][64]
    float* W21s = sm + 24704;    // [k][64]
    float* W12s = sm + 32896;    // [k][64]
    float* w11S = sm + 36992;    // [t][65]
    float* b11s = sm + 45312;
    float* b21s = sm + 45376;
    float* b12s = sm + 45440;

    const int tid = threadIdx.x;
    const int t0  = blockIdx.x * TILE;

    for (int idx = tid; idx < TILE * 64; idx += 256) {
        int t = idx >> 6, c = idx & 63;
        catS[t * 129 + c]      = img[(t0 + t) * 64 + c];
        catS[t * 129 + 64 + c] = loc[(t0 + t) * 64 + c];
    }
    for (int idx = tid; idx < 8192; idx += 256) {
        W11s[idx] = W11[idx];
        W21s[idx] = W21[idx];
    }
    for (int idx = tid; idx < 4096; idx += 256) W12s[idx] = W12[idx];
    if (tid < 64) { b11s[tid] = b11[tid]; b21s[tid] = b21[tid]; b12s[tid] = b12[tid]; }
    __syncthreads();

    const int tg = tid >> 3, og = tid & 7;
    const int tb = tg * 4, ob = og * 8;

    float a1[4][8], a2[4][8];
    #pragma unroll
    for (int t = 0; t < 4; t++)
        #pragma unroll
        for (int o = 0; o < 8; o++) { a1[t][o] = 0.f; a2[t][o] = 0.f; }

    #pragma unroll 8
    for (int k = 0; k < 128; k++) {
        float av[4];
        #pragma unroll
        for (int t = 0; t < 4; t++) av[t] = catS[(tb + t) * 129 + k];
        float4 u0 = *(float4*)&W11s[k * 64 + ob];
        float4 u1 = *(float4*)&W11s[k * 64 + ob + 4];
        float4 v0 = *(float4*)&W21s[k * 64 + ob];
        float4 v1 = *(float4*)&W21s[k * 64 + ob + 4];
        float ub[8] = {u0.x,u0.y,u0.z,u0.w,u1.x,u1.y,u1.z,u1.w};
        float vb[8] = {v0.x,v0.y,v0.z,v0.w,v1.x,v1.y,v1.z,v1.w};
        #pragma unroll
        for (int t = 0; t < 4; t++)
            #pragma unroll
            for (int o = 0; o < 8; o++) {
                a1[t][o] = fmaf(av[t], ub[o], a1[t][o]);
                a2[t][o] = fmaf(av[t], vb[o], a2[t][o]);
            }
    }

    #pragma unroll
    for (int t = 0; t < 4; t++)
        #pragma unroll
        for (int o = 0; o < 8; o++) {
            float v1 = fmaxf(a1[t][o] + b11s[ob + o], 0.f);
            w11S[(tb + t) * 65 + ob + o] = v1;
            float v2 = fmaxf(a2[t][o] + b21s[ob + o], 0.f);
            g_w21[(t0 + tb + t) * 64 + ob + o] = v2;
        }
    __syncthreads();

    float a3[4][8];
    #pragma unroll
    for (int t = 0; t < 4; t++)
        #pragma unroll
        for (int o = 0; o < 8; o++) a3[t][o] = 0.f;

    #pragma unroll 8
    for (int k = 0; k < 64; k++) {
        float av[4];
        #pragma unroll
        for (int t = 0; t < 4; t++) av[t] = w11S[(tb + t) * 65 + k];
        float4 u0 = *(float4*)&W12s[k * 64 + ob];
        float4 u1 = *(float4*)&W12s[k * 64 + ob + 4];
        float ub[8] = {u0.x,u0.y,u0.z,u0.w,u1.x,u1.y,u1.z,u1.w};
        #pragma unroll
        for (int t = 0; t < 4; t++)
            #pragma unroll
            for (int o = 0; o < 8; o++)
                a3[t][o] = fmaf(av[t], ub[o], a3[t][o]);
    }
    #pragma unroll
    for (int t = 0; t < 4; t++)
        #pragma unroll
        for (int o = 0; o < 8; o++)
            g_w12[(t0 + tb + t) * 64 + ob + o] = a3[t][o] + b12s[ob + o];
}

// ---------------------------------------------------------------------------
// Kernel B: X = A @ W22flat (+ w12 @ b22mat), LN + ReLU, out = Y @ W3 + b3
//   A[t, j*64+i] = w21[t,j] * w12[t,i]  (generated per-j into smem)
// smem (floats): w12s[128][65]@0  w21s@8320  As[64][128]@16640
//                Bs[2][4096]@24832  ys[128][65]@33024  W3s@41344
//                lnG@45440 lnB@45504 b3@45568 ; total 45632 floats = 182528 B
// ---------------------------------------------------------------------------
__global__ __launch_bounds__(256) void main_kernel(
    const float* __restrict__ W22, const float* __restrict__ b22,
    const float* __restrict__ lnG, const float* __restrict__ lnB,
    const float* __restrict__ W3,  const float* __restrict__ b3,
    float* __restrict__ out)
{
    extern __shared__ float sm[];
    float* w12s = sm;            // [t][65]
    float* w21s = sm + 8320;     // [t][65]
    float* As   = sm + 16640;    // [i][128]
    float* Bs   = sm + 24832;    // [2][64][64]
    float* ys   = sm + 33024;    // [t][65]
    float* W3s  = sm + 41344;    // [k][64]
    float* lnGs = sm + 45440;
    float* lnBs = sm + 45504;
    float* b3s  = sm + 45568;

    const int tid = threadIdx.x;
    const int t0  = blockIdx.x * TILE;

    for (int idx = tid; idx < TILE * 64; idx += 256) {
        int t = idx >> 6, c = idx & 63;
        w12s[t * 65 + c] = g_w12[(t0 + t) * 64 + c];
        w21s[t * 65 + c] = g_w21[(t0 + t) * 64 + c];
    }
    for (int idx = tid; idx < 4096; idx += 256) W3s[idx] = W3[idx];
    // preload Bs[0] = W22 row j=0 (viewed as [64 i][64 o])
    for (int idx = tid; idx < 1024; idx += 256)
        *(float4*)&Bs[idx * 4] = *(const float4*)&W22[idx * 4];
    if (tid < 64) { lnGs[tid] = lnG[tid]; lnBs[tid] = lnB[tid]; b3s[tid] = b3[tid]; }
    __syncthreads();

    const int tg = tid >> 4, og = tid & 15;
    const int tb = tg * 8, ob = og * 4;

    float acc[8][4];
    #pragma unroll
    for (int t = 0; t < 8; t++)
        #pragma unroll
        for (int o = 0; o < 4; o++) acc[t][o] = 0.f;

    int buf = 0;
    for (int j = 0; j <= 64; j++) {
        // ---- generate As[i][t] = (j<64 ? w21[t][j] : 1) * w12[t][i] ----
        #pragma unroll
        for (int r = 0; r < 8; r++) {
            int v  = r * 256 + tid;
            int i  = v >> 5;
            int t4 = (v & 31) * 4;
            float4 w;
            w.x = w12s[(t4 + 0) * 65 + i];
            w.y = w12s[(t4 + 1) * 65 + i];
            w.z = w12s[(t4 + 2) * 65 + i];
            w.w = w12s[(t4 + 3) * 65 + i];
            if (j < 64) {
                w.x *= w21s[(t4 + 0) * 65 + j];
                w.y *= w21s[(t4 + 1) * 65 + j];
                w.z *= w21s[(t4 + 2) * 65 + j];
                w.w *= w21s[(t4 + 3) * 65 + j];
            }
            *(float4*)&As[i * 128 + t4] = w;
        }
        __syncthreads();

        // ---- prefetch next B panel (W22 row j+1, or b22 at the end) ----
        float4 pf0, pf1, pf2, pf3;
        const bool hasNext = (j < 64);
        if (hasNext) {
            const float* src = (j < 63) ? (W22 + (j + 1) * 4096) : b22;
            pf0 = *(const float4*)(src + tid * 16);
            pf1 = *(const float4*)(src + tid * 16 + 4);
            pf2 = *(const float4*)(src + tid * 16 + 8);
            pf3 = *(const float4*)(src + tid * 16 + 12);
        }

        // ---- main FMA microkernel: acc[T,O] += As[:,T]^T @ Bs ----
        const float* Bcur = Bs + buf * 4096;
        #pragma unroll 16
        for (int i = 0; i < 64; i++) {
            float4 a0 = *(float4*)&As[i * 128 + tb];
            float4 a1 = *(float4*)&As[i * 128 + tb + 4];
            float4 bv = *(float4*)&Bcur[i * 64 + ob];
            float aa[8] = {a0.x,a0.y,a0.z,a0.w,a1.x,a1.y,a1.z,a1.w};
            float bb[4] = {bv.x,bv.y,bv.z,bv.w};
            #pragma unroll
            for (int t = 0; t < 8; t++)
                #pragma unroll
                for (int o = 0; o < 4; o++)
                    acc[t][o] = fmaf(aa[t], bb[o], acc[t][o]);
        }

        if (hasNext) {
            float* dst = Bs + (buf ^ 1) * 4096 + tid * 16;
            *(float4*)(dst)      = pf0;
            *(float4*)(dst + 4)  = pf1;
            *(float4*)(dst + 8)  = pf2;
            *(float4*)(dst + 12) = pf3;
        }
        __syncthreads();
        buf ^= 1;
    }

    // ---- fused LayerNorm + ReLU (token's 64 values live in 16 lanes) ----
    #pragma unroll
    for (int t = 0; t < 8; t++) {
        float s = acc[t][0] + acc[t][1] + acc[t][2] + acc[t][3];
        s += __shfl_xor_sync(0xffffffffu, s, 8);
        s += __shfl_xor_sync(0xffffffffu, s, 4);
        s += __shfl_xor_sync(0xffffffffu, s, 2);
        s += __shfl_xor_sync(0xffffffffu, s, 1);
        float mu = s * (1.0f / 64.0f);
        float d0 = acc[t][0] - mu, d1 = acc[t][1] - mu;
        float d2 = acc[t][2] - mu, d3 = acc[t][3] - mu;
        float q = d0 * d0 + d1 * d1 + d2 * d2 + d3 * d3;
        q += __shfl_xor_sync(0xffffffffu, q, 8);
        q += __shfl_xor_sync(0xffffffffu, q, 4);
        q += __shfl_xor_sync(0xffffffffu, q, 2);
        q += __shfl_xor_sync(0xffffffffu, q, 1);
        float rs = rsqrtf(q * (1.0f / 64.0f) + 1e-5f);
        float dd[4] = {d0, d1, d2, d3};
        #pragma unroll
        for (int o = 0; o < 4; o++) {
            float y = dd[o] * rs * lnGs[ob + o] + lnBs[ob + o];
            ys[(tb + t) * 65 + ob + o] = fmaxf(y, 0.f);
        }
    }
    __syncthreads();

    // ---- final linear: out = ys @ W3 + b3 ----
    float f[8][4];
    #pragma unroll
    for (int t = 0; t < 8; t++)
        #pragma unroll
        for (int o = 0; o < 4; o++) f[t][o] = b3s[ob + o];

    #pragma unroll 8
    for (int k = 0; k < 64; k++) {
        float av[8];
        #pragma unroll
        for (int t = 0; t < 8; t++) av[t] = ys[(tb + t) * 65 + k];
        float4 bv = *(float4*)&W3s[k * 64 + ob];
        float bb[4] = {bv.x, bv.y, bv.z, bv.w};
        #pragma unroll
        for (int t = 0; t < 8; t++)
            #pragma unroll
            for (int o = 0; o < 4; o++)
                f[t][o] = fmaf(av[t], bb[o], f[t][o]);
    }
    #pragma unroll
    for (int t = 0; t < 8; t++) {
        float4 v = make_float4(f[t][0], f[t][1], f[t][2], f[t][3]);
        *(float4*)&out[(t0 + tb + t) * 64 + ob] = v;
    }
}

// ---------------------------------------------------------------------------
extern "C" void kernel_launch(void* const* d_in, const int* in_sizes, int n_in,
                              void* d_out, int out_size)
{
    const float* img = (const float*)d_in[0];
    const float* loc = (const float*)d_in[1];
    const float* W11 = (const float*)d_in[2];
    const float* b11 = (const float*)d_in[3];
    const float* W12 = (const float*)d_in[4];
    const float* b12 = (const float*)d_in[5];
    const float* W21 = (const float*)d_in[6];
    const float* b21 = (const float*)d_in[7];
    const float* W22 = (const float*)d_in[8];
    const float* b22 = (const float*)d_in[9];
    const float* lnG = (const float*)d_in[10];
    const float* lnB = (const float*)d_in[11];
    const float* W3  = (const float*)d_in[12];
    const float* b3  = (const float*)d_in[13];
    float* out = (float*)d_out;

    const int smemA = 45504 * 4;
    const int smemB = 45632 * 4;
    cudaFuncSetAttribute(prep_kernel, cudaFuncAttributeMaxDynamicSharedMemorySize, smemA);
    cudaFuncSetAttribute(main_kernel, cudaFuncAttributeMaxDynamicSharedMemorySize, smemB);

    prep_kernel<<<NCTA, 256, smemA>>>(img, loc, W11, b11, W12, b12, W21, b21);
    main_kernel<<<NCTA, 256, smemB>>>(W22, b22, lnG, lnB, W3, b3, out);
}

// round 4
// speedup vs baseline: 3.8255x; 3.8255x over previous
#include <cuda_runtime.h>
#include <cuda_bf16.h>
#include <cstdint>

#define TOK_TOTAL 32768
#define TILE 128
#define NCTA (TOK_TOTAL / TILE)   // 256

// single extern shared symbol for all kernels
extern __shared__ __align__(128) uint8_t smbuf[];

// Intermediates
__device__ float g_w12[TOK_TOTAL * 64];
__device__ float g_w21[TOK_TOTAL * 64];
// Pre-packed B operands in mma.sync per-lane fragment order.
// g_Bpk[j] (16 KB): [hi 8KB | lo 8KB]; within each: (kc,nt) tile of 256 B =
//   lane*8 -> {reg0 = bf16x2 (k=i0, i0+1), reg1 = bf16x2 (k=i0+8, i0+9)},
//   i0 = kc*16 + (lane%4)*2, o = nt*8 + lane/4.
//   B[k=i][n=o] = W22[j, i*64+o]  (j=64 row: b22[i*64+o])
__device__ __align__(16) uint8_t g_Bpk[65 * 16384];
// W3 fragments, same scheme: B[k][n=o] = W3[k, o]
__device__ __align__(16) uint8_t g_W3pk[16384];

// ---------------------------------------------------------------------------
// helpers
// ---------------------------------------------------------------------------
__device__ __forceinline__ uint32_t smem_u32(const void* p) {
    uint32_t a;
    asm("{ .reg .u64 t; cvta.to.shared.u64 t, %1; cvt.u32.u64 %0, t; }" : "=r"(a) : "l"(p));
    return a;
}
__device__ __forceinline__ void cp16(uint32_t s, const void* g) {
    asm volatile("cp.async.cg.shared.global [%0], [%1], 16;" :: "r"(s), "l"(g));
}
// split f32 pair -> bf16x2 hi (lo half = v0) + bf16x2 lo (residuals)
__device__ __forceinline__ void split_pair(float v0, float v1, uint32_t& h, uint32_t& l) {
    asm("cvt.rn.bf16x2.f32 %0, %1, %2;" : "=r"(h) : "f"(v1), "f"(v0));
    float h0 = __uint_as_float(h << 16);
    float h1 = __uint_as_float(h & 0xffff0000u);
    asm("cvt.rn.bf16x2.f32 %0, %1, %2;" : "=r"(l) : "f"(v1 - h1), "f"(v0 - h0));
}

#define MMA_BF16(Cq, A, b0, b1)                                              \
    asm volatile("mma.sync.aligned.m16n8k16.row.col.f32.bf16.bf16.f32 "      \
                 "{%0,%1,%2,%3}, {%4,%5,%6,%7}, {%8,%9}, {%0,%1,%2,%3};"     \
                 : "+f"((Cq)[0]), "+f"((Cq)[1]), "+f"((Cq)[2]), "+f"((Cq)[3])\
                 : "r"((A)[0]), "r"((A)[1]), "r"((A)[2]), "r"((A)[3]),       \
                   "r"(b0), "r"(b1))

// ---------------------------------------------------------------------------
// Kernel A: w11 = relu(cat@W11+b11); w12 = w11@W12+b12; w21 = relu(cat@W21+b21)
// (fp32 FFMA version, known good)
// ---------------------------------------------------------------------------
__global__ __launch_bounds__(256) void prep_kernel(
    const float* __restrict__ img, const float* __restrict__ loc,
    const float* __restrict__ W11, const float* __restrict__ b11,
    const float* __restrict__ W12, const float* __restrict__ b12,
    const float* __restrict__ W21, const float* __restrict__ b21)
{
    float* sm = (float*)smbuf;
    float* catS = sm;            // [t][129]
    float* W11s = sm + 16512;
    float* W21s = sm + 24704;
    float* W12s = sm + 32896;
    float* w11S = sm + 36992;    // [t][65]
    float* b11s = sm + 45312;
    float* b21s = sm + 45376;
    float* b12s = sm + 45440;

    const int tid = threadIdx.x;
    const int t0  = blockIdx.x * TILE;

    for (int idx = tid; idx < TILE * 64; idx += 256) {
        int t = idx >> 6, c = idx & 63;
        catS[t * 129 + c]      = img[(t0 + t) * 64 + c];
        catS[t * 129 + 64 + c] = loc[(t0 + t) * 64 + c];
    }
    for (int idx = tid; idx < 8192; idx += 256) {
        W11s[idx] = W11[idx];
        W21s[idx] = W21[idx];
    }
    for (int idx = tid; idx < 4096; idx += 256) W12s[idx] = W12[idx];
    if (tid < 64) { b11s[tid] = b11[tid]; b21s[tid] = b21[tid]; b12s[tid] = b12[tid]; }
    __syncthreads();

    const int tg = tid >> 3, og = tid & 7;
    const int tb = tg * 4, ob = og * 8;

    float a1[4][8], a2[4][8];
    #pragma unroll
    for (int t = 0; t < 4; t++)
        #pragma unroll
        for (int o = 0; o < 8; o++) { a1[t][o] = 0.f; a2[t][o] = 0.f; }

    #pragma unroll 8
    for (int k = 0; k < 128; k++) {
        float av[4];
        #pragma unroll
        for (int t = 0; t < 4; t++) av[t] = catS[(tb + t) * 129 + k];
        float4 u0 = *(float4*)&W11s[k * 64 + ob];
        float4 u1 = *(float4*)&W11s[k * 64 + ob + 4];
        float4 v0 = *(float4*)&W21s[k * 64 + ob];
        float4 v1 = *(float4*)&W21s[k * 64 + ob + 4];
        float ub[8] = {u0.x,u0.y,u0.z,u0.w,u1.x,u1.y,u1.z,u1.w};
        float vb[8] = {v0.x,v0.y,v0.z,v0.w,v1.x,v1.y,v1.z,v1.w};
        #pragma unroll
        for (int t = 0; t < 4; t++)
            #pragma unroll
            for (int o = 0; o < 8; o++) {
                a1[t][o] = fmaf(av[t], ub[o], a1[t][o]);
                a2[t][o] = fmaf(av[t], vb[o], a2[t][o]);
            }
    }

    #pragma unroll
    for (int t = 0; t < 4; t++)
        #pragma unroll
        for (int o = 0; o < 8; o++) {
            float v1 = fmaxf(a1[t][o] + b11s[ob + o], 0.f);
            w11S[(tb + t) * 65 + ob + o] = v1;
            float v2 = fmaxf(a2[t][o] + b21s[ob + o], 0.f);
            g_w21[(t0 + tb + t) * 64 + ob + o] = v2;
        }
    __syncthreads();

    float a3[4][8];
    #pragma unroll
    for (int t = 0; t < 4; t++)
        #pragma unroll
        for (int o = 0; o < 8; o++) a3[t][o] = 0.f;

    #pragma unroll 8
    for (int k = 0; k < 64; k++) {
        float av[4];
        #pragma unroll
        for (int t = 0; t < 4; t++) av[t] = w11S[(tb + t) * 65 + k];
        float4 u0 = *(float4*)&W12s[k * 64 + ob];
        float4 u1 = *(float4*)&W12s[k * 64 + ob + 4];
        float ub[8] = {u0.x,u0.y,u0.z,u0.w,u1.x,u1.y,u1.z,u1.w};
        #pragma unroll
        for (int t = 0; t < 4; t++)
            #pragma unroll
            for (int o = 0; o < 8; o++)
                a3[t][o] = fmaf(av[t], ub[o], a3[t][o]);
    }
    #pragma unroll
    for (int t = 0; t < 4; t++)
        #pragma unroll
        for (int o = 0; o < 8; o++)
            g_w12[(t0 + tb + t) * 64 + ob + o] = a3[t][o] + b12s[ob + o];
}

// ---------------------------------------------------------------------------
// Convert kernel: pre-pack W22 (+b22 as j=64) and W3 into per-lane mma
// fragment order, bf16 hi/lo.
// ---------------------------------------------------------------------------
__global__ __launch_bounds__(256) void convert_kernel(
    const float* __restrict__ W22, const float* __restrict__ b22,
    const float* __restrict__ W3)
{
    int gid = blockIdx.x * 256 + threadIdx.x;
    if (gid < 65 * 1024) {
        int j  = gid >> 10;
        int r  = gid & 1023;
        int kc = r >> 8;
        int nt = (r >> 5) & 7;
        int l  = r & 31;
        int q2 = (l & 3) * 2;
        int o  = nt * 8 + (l >> 2);
        int i0 = kc * 16 + q2;
        const float* src = (j < 64) ? (W22 + j * 4096) : b22;
        float v0 = src[(i0    ) * 64 + o];
        float v1 = src[(i0 + 1) * 64 + o];
        float v2 = src[(i0 + 8) * 64 + o];
        float v3 = src[(i0 + 9) * 64 + o];
        uint32_t h0, l0, h1, l1;
        split_pair(v0, v1, h0, l0);
        split_pair(v2, v3, h1, l1);
        uint8_t* dst = g_Bpk + j * 16384 + (kc * 8 + nt) * 256 + l * 8;
        *(uint32_t*)(dst)            = h0;
        *(uint32_t*)(dst + 4)        = h1;
        *(uint32_t*)(dst + 8192)     = l0;
        *(uint32_t*)(dst + 8192 + 4) = l1;
    } else if (gid < 65 * 1024 + 1024) {
        int r  = gid - 65 * 1024;
        int kc = r >> 8;
        int nt = (r >> 5) & 7;
        int l  = r & 31;
        int q2 = (l & 3) * 2;
        int o  = nt * 8 + (l >> 2);
        int k0 = kc * 16 + q2;
        float v0 = W3[(k0    ) * 64 + o];
        float v1 = W3[(k0 + 1) * 64 + o];
        float v2 = W3[(k0 + 8) * 64 + o];
        float v3 = W3[(k0 + 9) * 64 + o];
        uint32_t h0, l0, h1, l1;
        split_pair(v0, v1, h0, l0);
        split_pair(v2, v3, h1, l1);
        uint8_t* dst = g_W3pk + (kc * 8 + nt) * 256 + l * 8;
        *(uint32_t*)(dst)            = h0;
        *(uint32_t*)(dst + 4)        = h1;
        *(uint32_t*)(dst + 8192)     = l0;
        *(uint32_t*)(dst + 8192 + 4) = l1;
    }
}

// ---------------------------------------------------------------------------
// Main kernel: 128 tokens / CTA, 256 threads (8 warps, 16 tokens each).
// X = A @ Bflat via mma.sync bf16 3-term; A fragments built in registers.
// Fused LN + ReLU + (y @ W3 + b3) epilogue, all in registers.
// smem: Bst[2][16KB] @0; w12s[128][66]f @32768; w21Ts[65][130]f @66560;
//       lnG @100360; lnB @100616; b3 @100872 ; total 101128 -> 101376
// ---------------------------------------------------------------------------
#define S_BST   0u
#define S_W12   32768u
#define S_W21T  66560u
#define S_LNG   100360u
#define S_LNB   100616u
#define S_B3    100872u
#define S_SZ    101376u

__global__ __launch_bounds__(256) void main_kernel(
    const float* __restrict__ lnG, const float* __restrict__ lnB,
    const float* __restrict__ b3,  float* __restrict__ out)
{
    float* w12s  = (float*)(smbuf + S_W12);
    float* w21Ts = (float*)(smbuf + S_W21T);
    float* lnGs  = (float*)(smbuf + S_LNG);
    float* lnBs  = (float*)(smbuf + S_LNB);
    float* b3s   = (float*)(smbuf + S_B3);
    const uint32_t sb = smem_u32(smbuf);

    const int tid = threadIdx.x;
    const int l   = tid & 31;
    const int w   = tid >> 5;
    const int t0  = blockIdx.x * TILE;
    const int wb  = w * 16;
    const int g   = l >> 2;          // groupID
    const int q2  = (l & 3) * 2;
    const int ta  = wb + g;          // local row of a0/a2 elems
    const int tb  = ta + 8;          // local row of a1/a3 elems

    // stage w12 (row layout, pad 66) and w21 transposed (w21Ts[j][t], pad 130)
    for (int idx = tid; idx < 2048; idx += 256) {
        int t = idx >> 4, c = (idx & 15) * 4;
        float4 a = *(const float4*)&g_w12[(t0 + t) * 64 + c];
        float4 b = *(const float4*)&g_w21[(t0 + t) * 64 + c];
        w12s[t * 66 + c + 0] = a.x;
        w12s[t * 66 + c + 1] = a.y;
        w12s[t * 66 + c + 2] = a.z;
        w12s[t * 66 + c + 3] = a.w;
        w21Ts[(c + 0) * 130 + t] = b.x;
        w21Ts[(c + 1) * 130 + t] = b.y;
        w21Ts[(c + 2) * 130 + t] = b.z;
        w21Ts[(c + 3) * 130 + t] = b.w;
    }
    if (tid < 64) { lnGs[tid] = lnG[tid]; lnBs[tid] = lnB[tid]; b3s[tid] = b3[tid]; }
    __syncthreads();

    // lane-private w12 values: per kc the 4 i-values this lane's A elems need
    float w12a[16], w12b[16];
    #pragma unroll
    for (int kc = 0; kc < 4; kc++) {
        int i0 = kc * 16 + q2;
        w12a[kc*4+0] = w12s[ta*66 + i0];
        w12a[kc*4+1] = w12s[ta*66 + i0 + 1];
        w12a[kc*4+2] = w12s[ta*66 + i0 + 8];
        w12a[kc*4+3] = w12s[ta*66 + i0 + 9];
        w12b[kc*4+0] = w12s[tb*66 + i0];
        w12b[kc*4+1] = w12s[tb*66 + i0 + 1];
        w12b[kc*4+2] = w12s[tb*66 + i0 + 8];
        w12b[kc*4+3] = w12s[tb*66 + i0 + 9];
    }

    float C[8][4];
    #pragma unroll
    for (int nt = 0; nt < 8; nt++)
        #pragma unroll
        for (int k = 0; k < 4; k++) C[nt][k] = 0.f;

    // preload B stage 0
    {
        const uint8_t* gB = g_Bpk;
        #pragma unroll
        for (int qq = 0; qq < 4; qq++)
            cp16(sb + S_BST + qq * 4096 + tid * 16, gB + qq * 4096 + tid * 16);
        asm volatile("cp.async.commit_group;" ::: "memory");
    }

    for (int j = 0; j <= 64; j++) {
        const int s = j & 1;
        if (j < 64) {
            const uint8_t* gB = g_Bpk + (j + 1) * 16384;
            uint32_t dstb = sb + S_BST + (s ^ 1) * 16384;
            #pragma unroll
            for (int qq = 0; qq < 4; qq++)
                cp16(dstb + qq * 4096 + tid * 16, gB + qq * 4096 + tid * 16);
            asm volatile("cp.async.commit_group;" ::: "memory");
            asm volatile("cp.async.wait_group 1;" ::: "memory");
        } else {
            asm volatile("cp.async.wait_group 0;" ::: "memory");
        }
        __syncthreads();

        float wva = 1.f, wvb = 1.f;
        if (j < 64) { wva = w21Ts[j * 130 + ta]; wvb = w21Ts[j * 130 + tb]; }
        const uint32_t bbase = sb + S_BST + s * 16384;

        #pragma unroll
        for (int kc = 0; kc < 4; kc++) {
            uint32_t ah[4], al[4];
            split_pair(wva * w12a[kc*4+0], wva * w12a[kc*4+1], ah[0], al[0]);
            split_pair(wvb * w12b[kc*4+0], wvb * w12b[kc*4+1], ah[1], al[1]);
            split_pair(wva * w12a[kc*4+2], wva * w12a[kc*4+3], ah[2], al[2]);
            split_pair(wvb * w12b[kc*4+2], wvb * w12b[kc*4+3], ah[3], al[3]);
            #pragma unroll
            for (int nt = 0; nt < 8; nt++) {
                uint32_t bh0, bh1, bl0, bl1;
                uint32_t addr = bbase + (kc * 8 + nt) * 256 + l * 8;
                asm("ld.shared.v2.b32 {%0,%1}, [%2];" : "=r"(bh0), "=r"(bh1) : "r"(addr));
                asm("ld.shared.v2.b32 {%0,%1}, [%2];" : "=r"(bl0), "=r"(bl1) : "r"(addr + 8192));
                MMA_BF16(C[nt], ah, bh0, bh1);
                MMA_BF16(C[nt], ah, bl0, bl1);
                MMA_BF16(C[nt], al, bh0, bh1);
            }
        }
        __syncthreads();
    }

    // ---- LayerNorm + ReLU in registers (quad shuffles over lanes l%4) ----
    {
        float sa = 0.f, sb2 = 0.f;
        #pragma unroll
        for (int nt = 0; nt < 8; nt++) { sa += C[nt][0] + C[nt][1]; sb2 += C[nt][2] + C[nt][3]; }
        sa  += __shfl_xor_sync(0xffffffffu, sa, 1);
        sa  += __shfl_xor_sync(0xffffffffu, sa, 2);
        sb2 += __shfl_xor_sync(0xffffffffu, sb2, 1);
        sb2 += __shfl_xor_sync(0xffffffffu, sb2, 2);
        float mua = sa * (1.0f / 64.0f), mub = sb2 * (1.0f / 64.0f);
        float qa = 0.f, qb = 0.f;
        #pragma unroll
        for (int nt = 0; nt < 8; nt++) {
            C[nt][0] -= mua; C[nt][1] -= mua; C[nt][2] -= mub; C[nt][3] -= mub;
            qa = fmaf(C[nt][0], C[nt][0], qa); qa = fmaf(C[nt][1], C[nt][1], qa);
            qb = fmaf(C[nt][2], C[nt][2], qb); qb = fmaf(C[nt][3], C[nt][3], qb);
        }
        qa += __shfl_xor_sync(0xffffffffu, qa, 1);
        qa += __shfl_xor_sync(0xffffffffu, qa, 2);
        qb += __shfl_xor_sync(0xffffffffu, qb, 1);
        qb += __shfl_xor_sync(0xffffffffu, qb, 2);
        float rsa = rsqrtf(qa * (1.0f / 64.0f) + 1e-5f);
        float rsb = rsqrtf(qb * (1.0f / 64.0f) + 1e-5f);
        #pragma unroll
        for (int nt = 0; nt < 8; nt++) {
            int col = nt * 8 + q2;
            float g0 = lnGs[col], g1 = lnGs[col + 1];
            float be0 = lnBs[col], be1 = lnBs[col + 1];
            C[nt][0] = fmaxf(fmaf(C[nt][0] * rsa, g0, be0), 0.f);
            C[nt][1] = fmaxf(fmaf(C[nt][1] * rsa, g1, be1), 0.f);
            C[nt][2] = fmaxf(fmaf(C[nt][2] * rsb, g0, be0), 0.f);
            C[nt][3] = fmaxf(fmaf(C[nt][3] * rsb, g1, be1), 0.f);
        }
    }

    // ---- out = y @ W3 + b3 : C fragments double as A fragments ----
    {
        uint32_t ah2[4][4], al2[4][4];
        #pragma unroll
        for (int kc = 0; kc < 4; kc++) {
            split_pair(C[2*kc][0],   C[2*kc][1],   ah2[kc][0], al2[kc][0]);
            split_pair(C[2*kc][2],   C[2*kc][3],   ah2[kc][1], al2[kc][1]);
            split_pair(C[2*kc+1][0], C[2*kc+1][1], ah2[kc][2], al2[kc][2]);
            split_pair(C[2*kc+1][2], C[2*kc+1][3], ah2[kc][3], al2[kc][3]);
        }
        float D[8][4];
        #pragma unroll
        for (int nt = 0; nt < 8; nt++)
            #pragma unroll
            for (int k = 0; k < 4; k++) D[nt][k] = 0.f;

        #pragma unroll
        for (int kc = 0; kc < 4; kc++) {
            #pragma unroll
            for (int nt = 0; nt < 8; nt++) {
                const uint8_t* p = g_W3pk + (kc * 8 + nt) * 256 + l * 8;
                uint2 bh = *(const uint2*)(p);
                uint2 bl = *(const uint2*)(p + 8192);
                MMA_BF16(D[nt], ah2[kc], bh.x, bh.y);
                MMA_BF16(D[nt], ah2[kc], bl.x, bl.y);
                MMA_BF16(D[nt], al2[kc], bh.x, bh.y);
            }
        }

        float* outA = out + (t0 + ta) * 64;
        float* outB = out + (t0 + tb) * 64;
        #pragma unroll
        for (int nt = 0; nt < 8; nt++) {
            int col = nt * 8 + q2;
            float b30 = b3s[col], b31 = b3s[col + 1];
            float2 va = make_float2(D[nt][0] + b30, D[nt][1] + b31);
            float2 vb = make_float2(D[nt][2] + b30, D[nt][3] + b31);
            *(float2*)(outA + col) = va;
            *(float2*)(outB + col) = vb;
        }
    }
}

// ---------------------------------------------------------------------------
extern "C" void kernel_launch(void* const* d_in, const int* in_sizes, int n_in,
                              void* d_out, int out_size)
{
    const float* img = (const float*)d_in[0];
    const float* loc = (const float*)d_in[1];
    const float* W11 = (const float*)d_in[2];
    const float* b11 = (const float*)d_in[3];
    const float* W12 = (const float*)d_in[4];
    const float* b12 = (const float*)d_in[5];
    const float* W21 = (const float*)d_in[6];
    const float* b21 = (const float*)d_in[7];
    const float* W22 = (const float*)d_in[8];
    const float* b22 = (const float*)d_in[9];
    const float* lnG = (const float*)d_in[10];
    const float* lnB = (const float*)d_in[11];
    const float* W3  = (const float*)d_in[12];
    const float* b3  = (const float*)d_in[13];
    float* out = (float*)d_out;

    const int smemA = 45504 * 4;
    cudaFuncSetAttribute(prep_kernel, cudaFuncAttributeMaxDynamicSharedMemorySize, smemA);
    cudaFuncSetAttribute(main_kernel, cudaFuncAttributeMaxDynamicSharedMemorySize, (int)S_SZ);

    convert_kernel<<<264, 256>>>(W22, b22, W3);
    prep_kernel<<<NCTA, 256, smemA>>>(img, loc, W11, b11, W12, b12, W21, b21);
    main_kernel<<<NCTA, 256, S_SZ>>>(lnG, lnB, b3, out);
}